// round 1
// baseline (speedup 1.0000x reference)
#include <cuda_runtime.h>
#include <math.h>

#define B_ 2
#define S_ 2048
#define E_ 1024
#define H_ 16
#define D_ 64

// Scratch (device globals — no allocation allowed in kernel_launch)
__device__ float g_Q [B_ * S_ * E_];   // [B,H,S,D]
__device__ float g_Kt[B_ * S_ * E_];   // [B,H,D,S]  (pre-transposed K)
__device__ float g_V [B_ * S_ * E_];   // [B,H,S,D]
__device__ float g_AO[B_ * S_ * E_];   // [B,S,E]

#define BM 64
#define BN 64
#define BK 32

// C = A[M,K] @ Bw[N,K]^T   (both K-contiguous, i.e. y = x @ W.T)
// MODE 0: plain C[M,N]; MODE 1: head-split [B,H,S,D]; MODE 2: head-split transposed [B,H,D,S]
template <int MODE>
__global__ __launch_bounds__(256) void gemm_nt_k(const float* __restrict__ A,
                                                 const float* __restrict__ Bw,
                                                 float* __restrict__ C) {
    const int M = B_ * S_, N = E_, K = E_;
    (void)M;
    __shared__ float As[BM][BK];   // natural: reads are half-warp broadcasts
    __shared__ float Bs[BK][BN];   // transposed: float4 reads along N
    const int tid = threadIdx.x;
    const int tx = tid & 15, ty = tid >> 4;
    const int m0 = blockIdx.y * BM, n0 = blockIdx.x * BN;
    const int rb = ty * 4, cb = tx * 4;
    const int lr = tid >> 3, lc = (tid & 7) * 4;

    float acc[4][4] = {};

    for (int k0 = 0; k0 < K; k0 += BK) {
#pragma unroll
        for (int rr = 0; rr < 2; rr++) {
            const int r = lr + rr * 32;
            *(float4*)&As[r][lc] =
                *(const float4*)&A[(size_t)(m0 + r) * K + k0 + lc];
            float4 v = *(const float4*)&Bw[(size_t)(n0 + r) * K + k0 + lc];
            Bs[lc + 0][r] = v.x; Bs[lc + 1][r] = v.y;
            Bs[lc + 2][r] = v.z; Bs[lc + 3][r] = v.w;
        }
        __syncthreads();
#pragma unroll
        for (int k4 = 0; k4 < BK; k4 += 4) {
            float a[4][4];
#pragma unroll
            for (int i = 0; i < 4; i++)
                *(float4*)a[i] = *(const float4*)&As[rb + i][k4];
#pragma unroll
            for (int j = 0; j < 4; j++) {
                const float4 b = *(const float4*)&Bs[k4 + j][cb];
#pragma unroll
                for (int i = 0; i < 4; i++) {
                    acc[i][0] += a[i][j] * b.x;
                    acc[i][1] += a[i][j] * b.y;
                    acc[i][2] += a[i][j] * b.z;
                    acc[i][3] += a[i][j] * b.w;
                }
            }
        }
        __syncthreads();
    }

#pragma unroll
    for (int i = 0; i < 4; i++) {
        const int gr = m0 + rb + i;
        const int gc = n0 + cb;
        if (MODE == 0) {
            *(float4*)&C[(size_t)gr * N + gc] = *(float4*)acc[i];
        } else {
            const int b = gr >> 11, s = gr & 2047;
            const int h = gc >> 6, d = gc & 63;
            if (MODE == 1) {
                *(float4*)&C[((size_t)(b * H_ + h) * S_ + s) * D_ + d] =
                    *(float4*)acc[i];
            } else {  // MODE 2: [B,H,D,S]
#pragma unroll
                for (int j = 0; j < 4; j++)
                    C[((size_t)(b * H_ + h) * D_ + d + j) * S_ + s] = acc[i][j];
            }
        }
    }
}

// Flash-style attention. One block per (64-query tile, b*h). d = 64 fits one tile.
// Q scaled by 1/sqrt(64) at load. K arrives pre-transposed [D,S] so smem fills
// are plain coalesced copies. P reuses K's smem buffer -> 48 KB static smem.
__global__ __launch_bounds__(256) void attn_k(const float* __restrict__ Q,
                                              const float* __restrict__ Kt,
                                              const float* __restrict__ V,
                                              float* __restrict__ AO) {
    __shared__ float Qs[64][64];
    __shared__ float KP[64][64];   // K^T tile [d][key], later P tile [q][key]
    __shared__ float Vs[64][64];   // [key][d]

    const int tid = threadIdx.x;
    const int tx = tid & 15, ty = tid >> 4;
    const int rb = ty * 4, cb = tx * 4;
    const int bh = blockIdx.y;
    const int q0 = blockIdx.x * 64;

    const float* Qb  = Q  + (size_t)bh * S_ * D_;
    const float* Ktb = Kt + (size_t)bh * D_ * S_;
    const float* Vb  = V  + (size_t)bh * S_ * D_;

    // Load Q tile, folding in the 1/sqrt(d_k) scale
#pragma unroll
    for (int p = 0; p < 4; p++) {
        const int r = ty + p * 16;
        float4 v = *(const float4*)&Qb[(size_t)(q0 + r) * D_ + tx * 4];
        v.x *= 0.125f; v.y *= 0.125f; v.z *= 0.125f; v.w *= 0.125f;
        *(float4*)&Qs[r][tx * 4] = v;
    }

    float m[4], l[4], o[4][4];
#pragma unroll
    for (int i = 0; i < 4; i++) {
        m[i] = -1e30f; l[i] = 0.f;
#pragma unroll
        for (int j = 0; j < 4; j++) o[i][j] = 0.f;
    }

    for (int k0 = 0; k0 < S_; k0 += 64) {
        __syncthreads();  // prev readers of KP/Vs done (also orders Q store->read on iter 0)
#pragma unroll
        for (int p = 0; p < 4; p++) {
            const int r = ty + p * 16;
            *(float4*)&KP[r][tx * 4] =
                *(const float4*)&Ktb[(size_t)r * S_ + k0 + tx * 4];
            *(float4*)&Vs[r][tx * 4] =
                *(const float4*)&Vb[(size_t)(k0 + r) * D_ + tx * 4];
        }
        __syncthreads();

        // S = Qs @ K^T : s[i][j] over queries rb+i, keys cb+j
        float s[4][4] = {};
#pragma unroll
        for (int d4 = 0; d4 < 64; d4 += 4) {
            float a[4][4];
#pragma unroll
            for (int i = 0; i < 4; i++)
                *(float4*)a[i] = *(const float4*)&Qs[rb + i][d4];
#pragma unroll
            for (int j = 0; j < 4; j++) {
                const float4 b = *(const float4*)&KP[d4 + j][cb];
#pragma unroll
                for (int i = 0; i < 4; i++) {
                    s[i][0] += a[i][j] * b.x;
                    s[i][1] += a[i][j] * b.y;
                    s[i][2] += a[i][j] * b.z;
                    s[i][3] += a[i][j] * b.w;
                }
            }
        }

        // Online softmax. Row group = 16 lanes sharing ty (contiguous half-warp).
#pragma unroll
        for (int i = 0; i < 4; i++) {
            float rm = fmaxf(fmaxf(s[i][0], s[i][1]), fmaxf(s[i][2], s[i][3]));
#pragma unroll
            for (int w = 1; w < 16; w <<= 1)
                rm = fmaxf(rm, __shfl_xor_sync(0xffffffffu, rm, w));
            const float mn = fmaxf(m[i], rm);
            const float al = __expf(m[i] - mn);
            m[i] = mn;
            float rs = 0.f;
#pragma unroll
            for (int j = 0; j < 4; j++) {
                s[i][j] = __expf(s[i][j] - mn);
                rs += s[i][j];
            }
#pragma unroll
            for (int w = 1; w < 16; w <<= 1)
                rs += __shfl_xor_sync(0xffffffffu, rs, w);
            l[i] = l[i] * al + rs;
#pragma unroll
            for (int j = 0; j < 4; j++) o[i][j] *= al;
        }

        __syncthreads();  // everyone finished reading KP (as K^T)
#pragma unroll
        for (int i = 0; i < 4; i++)
            *(float4*)&KP[rb + i][cb] = *(float4*)s[i];  // KP now holds P
        __syncthreads();

        // O += P @ V
#pragma unroll
        for (int k4 = 0; k4 < 64; k4 += 4) {
            float a[4][4];
#pragma unroll
            for (int i = 0; i < 4; i++)
                *(float4*)a[i] = *(const float4*)&KP[rb + i][k4];
#pragma unroll
            for (int j = 0; j < 4; j++) {
                const float4 b = *(const float4*)&Vs[k4 + j][cb];
#pragma unroll
                for (int i = 0; i < 4; i++) {
                    o[i][0] += a[i][j] * b.x;
                    o[i][1] += a[i][j] * b.y;
                    o[i][2] += a[i][j] * b.z;
                    o[i][3] += a[i][j] * b.w;
                }
            }
        }
    }

    // Normalize and write to [B,S,E] (heads re-concatenated)
    const int b = bh >> 4, h = bh & 15;
#pragma unroll
    for (int i = 0; i < 4; i++) {
        const float inv = 1.0f / l[i];
        float4 v;
        v.x = o[i][0] * inv; v.y = o[i][1] * inv;
        v.z = o[i][2] * inv; v.w = o[i][3] * inv;
        *(float4*)&AO[((size_t)(b * S_ + q0 + rb + i)) * E_ + h * D_ + cb] = v;
    }
}

extern "C" void kernel_launch(void* const* d_in, const int* in_sizes, int n_in,
                              void* d_out, int out_size) {
    (void)in_sizes; (void)n_in; (void)out_size;
    const float* x  = (const float*)d_in[0];
    const float* wq = (const float*)d_in[1];
    const float* wk = (const float*)d_in[2];
    const float* wv = (const float*)d_in[3];
    const float* wo = (const float*)d_in[4];
    float* out = (float*)d_out;

    float *q, *kt, *v, *ao;
    cudaGetSymbolAddress((void**)&q,  g_Q);
    cudaGetSymbolAddress((void**)&kt, g_Kt);
    cudaGetSymbolAddress((void**)&v,  g_V);
    cudaGetSymbolAddress((void**)&ao, g_AO);

    const dim3 gp(E_ / BN, (B_ * S_) / BM);   // (16, 64)
    gemm_nt_k<1><<<gp, 256>>>(x, wq, q);      // Q  -> [B,H,S,D]
    gemm_nt_k<2><<<gp, 256>>>(x, wk, kt);     // K  -> [B,H,D,S] (transposed)
    gemm_nt_k<1><<<gp, 256>>>(x, wv, v);      // V  -> [B,H,S,D]
    attn_k<<<dim3(S_ / 64, B_ * H_), 256>>>(q, kt, v, ao);
    gemm_nt_k<0><<<gp, 256>>>(ao, wo, out);   // out = AO @ wo^T
}

// round 5
// speedup vs baseline: 1.0590x; 1.0590x over previous
#include <cuda_runtime.h>
#include <math.h>

#define B_ 2
#define S_ 2048
#define E_ 1024
#define H_ 16
#define D_ 64

typedef unsigned long long ULL;

// Scratch (device globals — no allocation allowed in kernel_launch)
__device__ float g_Q [B_ * S_ * E_];   // [B,H,S,D]
__device__ float g_Kt[B_ * S_ * E_];   // [B,H,D,S]  (pre-transposed K)
__device__ float g_V [B_ * S_ * E_];   // [B,H,S,D]
__device__ float g_AO[B_ * S_ * E_];   // [B,S,E]

// ---- packed fp32x2 helpers (SASS FFMA2 path; ptxas never auto-fuses) ----
__device__ __forceinline__ void fma2(ULL& d, ULL a, ULL b) {
    asm("fma.rn.f32x2 %0, %1, %2, %0;" : "+l"(d) : "l"(a), "l"(b));
}
__device__ __forceinline__ void mul2(ULL& d, ULL a) {
    asm("mul.rn.f32x2 %0, %0, %1;" : "+l"(d) : "l"(a));
}
__device__ __forceinline__ ULL splat2(float x) {
    ULL r;
    asm("mov.b64 %0, {%1, %1};" : "=l"(r) : "r"(__float_as_uint(x)));
    return r;
}
__device__ __forceinline__ ULL pack2(float x, float y) {
    ULL r;
    asm("mov.b64 %0, {%1, %2};" : "=l"(r)
        : "r"(__float_as_uint(x)), "r"(__float_as_uint(y)));
    return r;
}

// ============================================================================
// GEMM: C = A[M,K] @ Bw[N,K]^T.  128x128 block tile, BK=32, 256 threads,
// 8x8 per thread, accumulators packed along M as f32x2 pairs.
// MODE 0: plain C[M,N]; MODE 1: [B,H,S,D]; MODE 2: [B,H,D,S]
// ============================================================================
template <int MODE>
__global__ __launch_bounds__(256) void gemm_nt2(const float* __restrict__ A,
                                                const float* __restrict__ Bw,
                                                float* __restrict__ C) {
    __shared__ float As[32][128];   // [k][m]
    __shared__ float Bs[32][128];   // [k][n]
    const int tid = threadIdx.x;
    const int tx = tid & 15, ty = tid >> 4;
    const int rb = ty * 8, cb = tx * 8;
    const int m0 = blockIdx.y * 128, n0 = blockIdx.x * 128;
    const int lrow = tid >> 1;            // 0..127
    const int lk   = (tid & 1) * 16;      // 0 or 16

    ULL acc[4][8];
#pragma unroll
    for (int i = 0; i < 4; i++)
#pragma unroll
        for (int j = 0; j < 8; j++) acc[i][j] = 0ull;

    const float* pA = A  + (size_t)(m0 + lrow) * E_ + lk;
    const float* pB = Bw + (size_t)(n0 + lrow) * E_ + lk;

    float4 fa[4], fb[4];
#pragma unroll
    for (int u = 0; u < 4; u++) {
        fa[u] = *(const float4*)(pA + u * 4);
        fb[u] = *(const float4*)(pB + u * 4);
    }

    for (int k0 = 0; k0 < E_; k0 += 32) {
#pragma unroll
        for (int u = 0; u < 4; u++) {
            const int c = lk + u * 4;
            As[c + 0][lrow] = fa[u].x; As[c + 1][lrow] = fa[u].y;
            As[c + 2][lrow] = fa[u].z; As[c + 3][lrow] = fa[u].w;
            Bs[c + 0][lrow] = fb[u].x; Bs[c + 1][lrow] = fb[u].y;
            Bs[c + 2][lrow] = fb[u].z; Bs[c + 3][lrow] = fb[u].w;
        }
        __syncthreads();
        if (k0 + 32 < E_) {
#pragma unroll
            for (int u = 0; u < 4; u++) {
                fa[u] = *(const float4*)(pA + k0 + 32 + u * 4);
                fb[u] = *(const float4*)(pB + k0 + 32 + u * 4);
            }
        }
#pragma unroll
        for (int k = 0; k < 32; k++) {
            const ulonglong2 a01 = *(const ulonglong2*)&As[k][rb];
            const ulonglong2 a23 = *(const ulonglong2*)&As[k][rb + 4];
            const float4 b0 = *(const float4*)&Bs[k][cb];
            const float4 b1 = *(const float4*)&Bs[k][cb + 4];
            const ULL bs[8] = { splat2(b0.x), splat2(b0.y), splat2(b0.z), splat2(b0.w),
                                splat2(b1.x), splat2(b1.y), splat2(b1.z), splat2(b1.w) };
#pragma unroll
            for (int j = 0; j < 8; j++) {
                fma2(acc[0][j], a01.x, bs[j]);
                fma2(acc[1][j], a01.y, bs[j]);
                fma2(acc[2][j], a23.x, bs[j]);
                fma2(acc[3][j], a23.y, bs[j]);
            }
        }
        __syncthreads();
    }

#pragma unroll
    for (int ip = 0; ip < 4; ip++) {
#pragma unroll
        for (int h = 0; h < 2; h++) {
            const int gr = m0 + rb + ip * 2 + h;
            const int gc = n0 + cb;
            float v[8];
#pragma unroll
            for (int j = 0; j < 8; j++) v[j] = ((const float*)&acc[ip][j])[h];
            if (MODE == 0) {
                *(float4*)&C[(size_t)gr * E_ + gc]     = make_float4(v[0], v[1], v[2], v[3]);
                *(float4*)&C[(size_t)gr * E_ + gc + 4] = make_float4(v[4], v[5], v[6], v[7]);
            } else {
                const int b = gr >> 11, s = gr & 2047;
                const int hh = gc >> 6, d = gc & 63;
                if (MODE == 1) {
                    float* dst = &C[((size_t)(b * H_ + hh) * S_ + s) * D_ + d];
                    *(float4*)dst       = make_float4(v[0], v[1], v[2], v[3]);
                    *(float4*)(dst + 4) = make_float4(v[4], v[5], v[6], v[7]);
                } else {  // MODE 2: [B,H,D,S]
#pragma unroll
                    for (int j = 0; j < 8; j++)
                        C[((size_t)(b * H_ + hh) * D_ + d + j) * S_ + s] = v[j];
                }
            }
        }
    }
}

// ============================================================================
// Flash attention: 64 threads/block, 64q x 64k tile, 8x8 per thread, f32x2.
// Qt stored transposed [d][q] (conflict-free pair loads). KP holds K^T [d][key]
// during S-phase, then reused as P^T [key][q ^ (k&56)] (swizzled) for PV.
// ============================================================================
__global__ __launch_bounds__(64) void attn2(const float* __restrict__ Q,
                                            const float* __restrict__ Kt,
                                            const float* __restrict__ V,
                                            float* __restrict__ AO) {
    __shared__ float Qt[64][64];   // [d][q], scaled by 1/8
    __shared__ float KP[64][64];   // K^T [d][key]; later P^T [key][q^swz]
    __shared__ float Vs[64][64];   // [key][d]

    const int tid = threadIdx.x;
    const int tx = tid & 7, ty = tid >> 3;
    const int rb = ty * 8, cb = tx * 8;
    const int bh = blockIdx.y;
    const int q0 = blockIdx.x * 64;

    const float* Qb  = Q  + (size_t)bh * S_ * D_;
    const float* Ktb = Kt + (size_t)bh * D_ * S_;
    const float* Vb  = V  + (size_t)bh * S_ * D_;

    // Qt[d][q] = Q[q][d] * 0.125 ; scalar stores hit 32 distinct banks
#pragma unroll
    for (int c = 0; c < 64; c += 4) {
        float4 v = *(const float4*)&Qb[(size_t)(q0 + tid) * D_ + c];
        Qt[c + 0][tid] = v.x * 0.125f; Qt[c + 1][tid] = v.y * 0.125f;
        Qt[c + 2][tid] = v.z * 0.125f; Qt[c + 3][tid] = v.w * 0.125f;
    }

    ULL o2[4][8];
#pragma unroll
    for (int i = 0; i < 4; i++)
#pragma unroll
        for (int j = 0; j < 8; j++) o2[i][j] = 0ull;
    float m[8], l[8];
#pragma unroll
    for (int i = 0; i < 8; i++) { m[i] = -1e30f; l[i] = 0.f; }

    const int c4 = (tid & 15) * 4;   // fill: 16 lanes span a 64-float row
    const int d0 = tid >> 4;         // 4 rows per pass

    for (int k0 = 0; k0 < S_; k0 += 64) {
        __syncthreads();   // prior PV reads of KP/Vs done (also orders Qt fill)
#pragma unroll
        for (int t = 0; t < 16; t++) {
            const int d = d0 + t * 4;
            *(float4*)&KP[d][c4] = *(const float4*)&Ktb[(size_t)d * S_ + k0 + c4];
            *(float4*)&Vs[d][c4] = *(const float4*)&Vb[(size_t)(k0 + d) * D_ + c4];
        }
        __syncthreads();

        // ---- S = Q @ K^T : s2[4][8] = q-pairs x keys ----
        ULL s2[4][8];
#pragma unroll
        for (int i = 0; i < 4; i++)
#pragma unroll
            for (int j = 0; j < 8; j++) s2[i][j] = 0ull;

#pragma unroll 8
        for (int d = 0; d < 64; d++) {
            const ulonglong2 a01 = *(const ulonglong2*)&Qt[d][rb];
            const ulonglong2 a23 = *(const ulonglong2*)&Qt[d][rb + 4];
            const float4 b0 = *(const float4*)&KP[d][cb];
            const float4 b1 = *(const float4*)&KP[d][cb + 4];
            const ULL bs[8] = { splat2(b0.x), splat2(b0.y), splat2(b0.z), splat2(b0.w),
                                splat2(b1.x), splat2(b1.y), splat2(b1.z), splat2(b1.w) };
#pragma unroll
            for (int j = 0; j < 8; j++) {
                fma2(s2[0][j], a01.x, bs[j]);
                fma2(s2[1][j], a01.y, bs[j]);
                fma2(s2[2][j], a23.x, bs[j]);
                fma2(s2[3][j], a23.y, bs[j]);
            }
        }

        // ---- online softmax (register-only); sf aliases s2 as floats ----
        float* sf = (float*)s2;   // sf[(ip*8+j)*2 + h] = S[rb+2ip+h][cb+j]
        float al[8];
#pragma unroll
        for (int i = 0; i < 8; i++) {
            const int ip = i >> 1, h = i & 1;
            float rm = -1e30f;
#pragma unroll
            for (int j = 0; j < 8; j++) rm = fmaxf(rm, sf[(ip * 8 + j) * 2 + h]);
#pragma unroll
            for (int w = 1; w < 8; w <<= 1)
                rm = fmaxf(rm, __shfl_xor_sync(0xffffffffu, rm, w));
            const float mn = fmaxf(m[i], rm);
            al[i] = __expf(m[i] - mn);
            m[i] = mn;
            float rs = 0.f;
#pragma unroll
            for (int j = 0; j < 8; j++) {
                const float e = __expf(sf[(ip * 8 + j) * 2 + h] - mn);
                sf[(ip * 8 + j) * 2 + h] = e;
                rs += e;
            }
#pragma unroll
            for (int w = 1; w < 8; w <<= 1)
                rs += __shfl_xor_sync(0xffffffffu, rs, w);
            l[i] = l[i] * al[i] + rs;
        }
#pragma unroll
        for (int ip = 0; ip < 4; ip++) {
            const ULL alp = pack2(al[2 * ip], al[2 * ip + 1]);
#pragma unroll
            for (int j = 0; j < 8; j++) mul2(o2[ip][j], alp);
        }

        __syncthreads();   // all S-phase KP reads complete before P overwrite
        // store P^T: row = key cb+j, col = q ^ cb (swizzle kills bank conflicts)
#pragma unroll
        for (int j = 0; j < 8; j++)
#pragma unroll
            for (int i = 0; i < 8; i++)
                KP[cb + j][(rb + i) ^ cb] = sf[((i >> 1) * 8 + j) * 2 + (i & 1)];
        __syncthreads();

        // ---- O += P @ V : o2[4][8] = q-pairs x d-cols ----
#pragma unroll 8
        for (int k = 0; k < 64; k++) {
            const int sw = k & 56;
            const ulonglong2 a01 = *(const ulonglong2*)&KP[k][rb ^ sw];
            const ulonglong2 a23 = *(const ulonglong2*)&KP[k][(rb ^ sw) + 4];
            const float4 b0 = *(const float4*)&Vs[k][cb];
            const float4 b1 = *(const float4*)&Vs[k][cb + 4];
            const ULL bs[8] = { splat2(b0.x), splat2(b0.y), splat2(b0.z), splat2(b0.w),
                                splat2(b1.x), splat2(b1.y), splat2(b1.z), splat2(b1.w) };
#pragma unroll
            for (int j = 0; j < 8; j++) {
                fma2(o2[0][j], a01.x, bs[j]);
                fma2(o2[1][j], a01.y, bs[j]);
                fma2(o2[2][j], a23.x, bs[j]);
                fma2(o2[3][j], a23.y, bs[j]);
            }
        }
    }

    // normalize and write [B,S,E]
    const int b = bh >> 4, h = bh & 15;
#pragma unroll
    for (int i = 0; i < 8; i++) {
        const int ip = i >> 1, hh = i & 1;
        const float inv = 1.0f / l[i];
        float v[8];
#pragma unroll
        for (int j = 0; j < 8; j++) v[j] = ((const float*)&o2[ip][j])[hh] * inv;
        float* dst = &AO[((size_t)(b * S_ + q0 + rb + i)) * E_ + h * D_ + cb];
        *(float4*)dst       = make_float4(v[0], v[1], v[2], v[3]);
        *(float4*)(dst + 4) = make_float4(v[4], v[5], v[6], v[7]);
    }
}

extern "C" void kernel_launch(void* const* d_in, const int* in_sizes, int n_in,
                              void* d_out, int out_size) {
    (void)in_sizes; (void)n_in; (void)out_size;
    const float* x  = (const float*)d_in[0];
    const float* wq = (const float*)d_in[1];
    const float* wk = (const float*)d_in[2];
    const float* wv = (const float*)d_in[3];
    const float* wo = (const float*)d_in[4];
    float* out = (float*)d_out;

    float *q, *kt, *v, *ao;
    cudaGetSymbolAddress((void**)&q,  g_Q);
    cudaGetSymbolAddress((void**)&kt, g_Kt);
    cudaGetSymbolAddress((void**)&v,  g_V);
    cudaGetSymbolAddress((void**)&ao, g_AO);

    const dim3 gp(E_ / 128, (B_ * S_) / 128);   // (8, 32)
    gemm_nt2<1><<<gp, 256>>>(x, wq, q);      // Q  -> [B,H,S,D]
    gemm_nt2<2><<<gp, 256>>>(x, wk, kt);     // K  -> [B,H,D,S]
    gemm_nt2<1><<<gp, 256>>>(x, wv, v);      // V  -> [B,H,S,D]
    attn2<<<dim3(S_ / 64, B_ * H_), 64>>>(q, kt, v, ao);
    gemm_nt2<0><<<gp, 256>>>(ao, wo, out);   // out = AO @ wo^T
}

// round 9
// speedup vs baseline: 1.5763x; 1.4885x over previous
#include <cuda_runtime.h>
#include <math.h>

#define B_ 2
#define S_ 2048
#define E_ 1024
#define H_ 16
#define D_ 64

typedef unsigned int u32;

// Scratch (device globals — no allocation allowed in kernel_launch)
__device__ float g_Q [B_ * S_ * E_];   // [B,H,S,D]
__device__ float g_Kt[B_ * S_ * E_];   // [B,H,D,S]
__device__ float g_V [B_ * S_ * E_];   // [B,H,S,D]
__device__ float g_AO[B_ * S_ * E_];   // [B,S,E]

__device__ __forceinline__ float tf32r(float x) {   // round-to-nearest tf32
    u32 r; asm("cvt.rna.tf32.f32 %0, %1;" : "=r"(r) : "f"(x));
    return __uint_as_float(r);
}
// D += A(16x8, row) * B(8x8, col)  -- tf32 inputs, fp32 accum. sm_80+ feature.
__device__ __forceinline__ void mma8(float* c, const u32* a, const u32* b) {
    asm volatile(
        "mma.sync.aligned.m16n8k8.row.col.f32.tf32.tf32.f32 "
        "{%0,%1,%2,%3}, {%4,%5,%6,%7}, {%8,%9}, {%0,%1,%2,%3};"
        : "+f"(c[0]), "+f"(c[1]), "+f"(c[2]), "+f"(c[3])
        : "r"(a[0]), "r"(a[1]), "r"(a[2]), "r"(a[3]), "r"(b[0]), "r"(b[1]));
}

// ============================================================================
// tf32 mma.sync GEMM: C[4096,1024] = A[M,K] @ Bw[N,K]^T
// CTA tile 128x128, BK=32, 8 warps (2m x 4n), warp tile 64x32.
// smem [row][36] padding: stride 36 = 4 mod 32 -> all fragment loads and
// fills hit >=8 distinct bank groups (frag loads fully conflict-free).
// MODE 0: C[M,N]; MODE 1: [B,H,S,D]; MODE 2: [B,H,D,S]
// ============================================================================
template <int MODE>
__global__ __launch_bounds__(256) void gemm_mma(const float* __restrict__ A,
                                                const float* __restrict__ Bw,
                                                float* __restrict__ C) {
    __shared__ float As[128][36];   // [m][k]
    __shared__ float Bs[128][36];   // [n][k]

    const int tid = threadIdx.x;
    const int wid = tid >> 5, lane = tid & 31;
    const int g = lane >> 2, tig = lane & 3;     // mma group / thread-in-group
    const int wm = wid >> 2, wn = wid & 3;       // warp tile coords
    const int m0 = blockIdx.y * 128, n0 = blockIdx.x * 128;

    // fill mapping: 2 threads per 32-float row
    const int row = tid >> 1, half = tid & 1;
    const float* pA = A  + (size_t)(m0 + row) * E_ + half * 16;
    const float* pB = Bw + (size_t)(n0 + row) * E_ + half * 16;

    float acc[4][4][4];   // [mtile][ntile][reg]
#pragma unroll
    for (int i = 0; i < 4; i++)
#pragma unroll
        for (int j = 0; j < 4; j++)
#pragma unroll
            for (int r = 0; r < 4; r++) acc[i][j][r] = 0.f;

    float4 fa[4], fb[4];
#pragma unroll
    for (int u = 0; u < 4; u++) {
        fa[u] = *(const float4*)(pA + u * 4);
        fb[u] = *(const float4*)(pB + u * 4);
    }

    for (int c = 0; c < 32; c++) {
#pragma unroll
        for (int u = 0; u < 4; u++) {
            const int kc = half * 16 + u * 4;
            *(float4*)&As[row][kc] = make_float4(tf32r(fa[u].x), tf32r(fa[u].y),
                                                 tf32r(fa[u].z), tf32r(fa[u].w));
            *(float4*)&Bs[row][kc] = make_float4(tf32r(fb[u].x), tf32r(fb[u].y),
                                                 tf32r(fb[u].z), tf32r(fb[u].w));
        }
        __syncthreads();
        if (c + 1 < 32) {
#pragma unroll
            for (int u = 0; u < 4; u++) {
                fa[u] = *(const float4*)(pA + (c + 1) * 32 + u * 4);
                fb[u] = *(const float4*)(pB + (c + 1) * 32 + u * 4);
            }
        }
#pragma unroll
        for (int k8 = 0; k8 < 32; k8 += 8) {
            u32 a[4][4], b[4][2];
#pragma unroll
            for (int mi = 0; mi < 4; mi++) {
                const int r = wm * 64 + mi * 16 + g;
                const u32* r0 = (const u32*)&As[r][k8 + tig];
                const u32* r1 = (const u32*)&As[r + 8][k8 + tig];
                a[mi][0] = r0[0]; a[mi][1] = r1[0];
                a[mi][2] = r0[4]; a[mi][3] = r1[4];
            }
#pragma unroll
            for (int ni = 0; ni < 4; ni++) {
                const int nn = wn * 32 + ni * 8 + g;
                const u32* r0 = (const u32*)&Bs[nn][k8 + tig];
                b[ni][0] = r0[0]; b[ni][1] = r0[4];
            }
#pragma unroll
            for (int mi = 0; mi < 4; mi++)
#pragma unroll
                for (int ni = 0; ni < 4; ni++)
                    mma8(acc[mi][ni], a[mi], b[ni]);
        }
        __syncthreads();
    }

    // ------------------------------ epilogue ------------------------------
    // lane holds C rows {base+g, base+g+8}, cols {2*tig, 2*tig+1} per tile.
#pragma unroll
    for (int mi = 0; mi < 4; mi++) {
#pragma unroll
        for (int hh = 0; hh < 2; hh++) {
            const int mg = m0 + wm * 64 + mi * 16 + g + hh * 8;
#pragma unroll
            for (int ni = 0; ni < 4; ni++) {
                const int col = n0 + wn * 32 + ni * 8 + 2 * tig;
                const float v0 = acc[mi][ni][hh * 2 + 0];
                const float v1 = acc[mi][ni][hh * 2 + 1];
                if (MODE == 0) {
                    *(float2*)&C[(size_t)mg * E_ + col] = make_float2(v0, v1);
                } else {
                    const int b = mg >> 11, s = mg & 2047;
                    const int h = col >> 6, d = col & 63;
                    if (MODE == 1) {
                        *(float2*)&C[((size_t)(b * H_ + h) * S_ + s) * D_ + d] =
                            make_float2(v0, v1);
                    } else {  // MODE 2: [B,H,D,S]
                        C[((size_t)(b * H_ + h) * D_ + d)     * S_ + s] = v0;
                        C[((size_t)(b * H_ + h) * D_ + d + 1) * S_ + s] = v1;
                    }
                }
            }
        }
    }
}

// ============================================================================
// Flash attention (round-1 version: 256 thr, 64x64 tile, 4x4/thread fp32)
// ============================================================================
__global__ __launch_bounds__(256) void attn_k(const float* __restrict__ Q,
                                              const float* __restrict__ Kt,
                                              const float* __restrict__ V,
                                              float* __restrict__ AO) {
    __shared__ float Qs[64][64];
    __shared__ float KP[64][64];
    __shared__ float Vs[64][64];

    const int tid = threadIdx.x;
    const int tx = tid & 15, ty = tid >> 4;
    const int rb = ty * 4, cb = tx * 4;
    const int bh = blockIdx.y;
    const int q0 = blockIdx.x * 64;

    const float* Qb  = Q  + (size_t)bh * S_ * D_;
    const float* Ktb = Kt + (size_t)bh * D_ * S_;
    const float* Vb  = V  + (size_t)bh * S_ * D_;

#pragma unroll
    for (int p = 0; p < 4; p++) {
        const int r = ty + p * 16;
        float4 v = *(const float4*)&Qb[(size_t)(q0 + r) * D_ + tx * 4];
        v.x *= 0.125f; v.y *= 0.125f; v.z *= 0.125f; v.w *= 0.125f;
        *(float4*)&Qs[r][tx * 4] = v;
    }

    float m[4], l[4], o[4][4];
#pragma unroll
    for (int i = 0; i < 4; i++) {
        m[i] = -1e30f; l[i] = 0.f;
#pragma unroll
        for (int j = 0; j < 4; j++) o[i][j] = 0.f;
    }

    for (int k0 = 0; k0 < S_; k0 += 64) {
        __syncthreads();
#pragma unroll
        for (int p = 0; p < 4; p++) {
            const int r = ty + p * 16;
            *(float4*)&KP[r][tx * 4] =
                *(const float4*)&Ktb[(size_t)r * S_ + k0 + tx * 4];
            *(float4*)&Vs[r][tx * 4] =
                *(const float4*)&Vb[(size_t)(k0 + r) * D_ + tx * 4];
        }
        __syncthreads();

        float s[4][4] = {};
#pragma unroll
        for (int d4 = 0; d4 < 64; d4 += 4) {
            float a[4][4];
#pragma unroll
            for (int i = 0; i < 4; i++)
                *(float4*)a[i] = *(const float4*)&Qs[rb + i][d4];
#pragma unroll
            for (int j = 0; j < 4; j++) {
                const float4 b = *(const float4*)&KP[d4 + j][cb];
#pragma unroll
                for (int i = 0; i < 4; i++) {
                    s[i][0] += a[i][j] * b.x;
                    s[i][1] += a[i][j] * b.y;
                    s[i][2] += a[i][j] * b.z;
                    s[i][3] += a[i][j] * b.w;
                }
            }
        }

#pragma unroll
        for (int i = 0; i < 4; i++) {
            float rm = fmaxf(fmaxf(s[i][0], s[i][1]), fmaxf(s[i][2], s[i][3]));
#pragma unroll
            for (int w = 1; w < 16; w <<= 1)
                rm = fmaxf(rm, __shfl_xor_sync(0xffffffffu, rm, w));
            const float mn = fmaxf(m[i], rm);
            const float al = __expf(m[i] - mn);
            m[i] = mn;
            float rs = 0.f;
#pragma unroll
            for (int j = 0; j < 4; j++) {
                s[i][j] = __expf(s[i][j] - mn);
                rs += s[i][j];
            }
#pragma unroll
            for (int w = 1; w < 16; w <<= 1)
                rs += __shfl_xor_sync(0xffffffffu, rs, w);
            l[i] = l[i] * al + rs;
#pragma unroll
            for (int j = 0; j < 4; j++) o[i][j] *= al;
        }

        __syncthreads();
#pragma unroll
        for (int i = 0; i < 4; i++)
            *(float4*)&KP[rb + i][cb] = *(float4*)s[i];
        __syncthreads();

#pragma unroll
        for (int k4 = 0; k4 < 64; k4 += 4) {
            float a[4][4];
#pragma unroll
            for (int i = 0; i < 4; i++)
                *(float4*)a[i] = *(const float4*)&KP[rb + i][k4];
#pragma unroll
            for (int j = 0; j < 4; j++) {
                const float4 b = *(const float4*)&Vs[k4 + j][cb];
#pragma unroll
                for (int i = 0; i < 4; i++) {
                    o[i][0] += a[i][j] * b.x;
                    o[i][1] += a[i][j] * b.y;
                    o[i][2] += a[i][j] * b.z;
                    o[i][3] += a[i][j] * b.w;
                }
            }
        }
    }

    const int b = bh >> 4, h = bh & 15;
#pragma unroll
    for (int i = 0; i < 4; i++) {
        const float inv = 1.0f / l[i];
        float4 v;
        v.x = o[i][0] * inv; v.y = o[i][1] * inv;
        v.z = o[i][2] * inv; v.w = o[i][3] * inv;
        *(float4*)&AO[((size_t)(b * S_ + q0 + rb + i)) * E_ + h * D_ + cb] = v;
    }
}

extern "C" void kernel_launch(void* const* d_in, const int* in_sizes, int n_in,
                              void* d_out, int out_size) {
    (void)in_sizes; (void)n_in; (void)out_size;
    const float* x  = (const float*)d_in[0];
    const float* wq = (const float*)d_in[1];
    const float* wk = (const float*)d_in[2];
    const float* wv = (const float*)d_in[3];
    const float* wo = (const float*)d_in[4];
    float* out = (float*)d_out;

    float *q, *kt, *v, *ao;
    cudaGetSymbolAddress((void**)&q,  g_Q);
    cudaGetSymbolAddress((void**)&kt, g_Kt);
    cudaGetSymbolAddress((void**)&v,  g_V);
    cudaGetSymbolAddress((void**)&ao, g_AO);

    const dim3 gp(E_ / 128, (B_ * S_) / 128);   // (8, 32)
    gemm_mma<1><<<gp, 256>>>(x, wq, q);      // Q  -> [B,H,S,D]
    gemm_mma<2><<<gp, 256>>>(x, wk, kt);     // K  -> [B,H,D,S]
    gemm_mma<1><<<gp, 256>>>(x, wv, v);      // V  -> [B,H,S,D]
    attn_k<<<dim3(S_ / 64, B_ * H_), 256>>>(q, kt, v, ao);
    gemm_mma<0><<<gp, 256>>>(ao, wo, out);   // out = AO @ wo^T
}

// round 10
// speedup vs baseline: 2.0517x; 1.3016x over previous
#include <cuda_runtime.h>
#include <math.h>

#define B_ 2
#define S_ 2048
#define E_ 1024
#define H_ 16
#define D_ 64

typedef unsigned int u32;

// Scratch (device globals — no allocation allowed in kernel_launch)
__device__ float g_Q [B_ * S_ * E_];   // [B,H,S,D]
__device__ float g_K [B_ * S_ * E_];   // [B,H,S,D]
__device__ float g_V [B_ * S_ * E_];   // [B,H,S,D]
__device__ float g_AO[B_ * S_ * E_];   // [B,S,E]

__device__ __forceinline__ u32 tf32b(float x) {   // tf32 (rna) bit pattern
    u32 r; asm("cvt.rna.tf32.f32 %0, %1;" : "=r"(r) : "f"(x));
    return r;
}
__device__ __forceinline__ float tf32r(float x) {
    return __uint_as_float(tf32b(x));
}
// D += A(16x8, row) * B(8x8, col)  -- tf32 inputs, fp32 accum (sm_80+ baseline)
__device__ __forceinline__ void mma8(float* c, const u32* a, const u32* b) {
    asm volatile(
        "mma.sync.aligned.m16n8k8.row.col.f32.tf32.tf32.f32 "
        "{%0,%1,%2,%3}, {%4,%5,%6,%7}, {%8,%9}, {%0,%1,%2,%3};"
        : "+f"(c[0]), "+f"(c[1]), "+f"(c[2]), "+f"(c[3])
        : "r"(a[0]), "r"(a[1]), "r"(a[2]), "r"(a[3]), "r"(b[0]), "r"(b[1]));
}
__device__ __forceinline__ void mma8v(float* c, u32 a0, u32 a1, u32 a2, u32 a3,
                                      u32 b0, u32 b1) {
    asm volatile(
        "mma.sync.aligned.m16n8k8.row.col.f32.tf32.tf32.f32 "
        "{%0,%1,%2,%3}, {%4,%5,%6,%7}, {%8,%9}, {%0,%1,%2,%3};"
        : "+f"(c[0]), "+f"(c[1]), "+f"(c[2]), "+f"(c[3])
        : "r"(a0), "r"(a1), "r"(a2), "r"(a3), "r"(b0), "r"(b1));
}

// ============================================================================
// tf32 mma.sync GEMM: C[4096,1024] = A[M,K] @ Bw[N,K]^T
// CTA tile 128x128, BK=32, 8 warps (2m x 4n), warp tile 64x32.
// MODE 0: C[M,N]; MODE 1: [B,H,S,D]
// ============================================================================
template <int MODE>
__global__ __launch_bounds__(256) void gemm_mma(const float* __restrict__ A,
                                                const float* __restrict__ Bw,
                                                float* __restrict__ C) {
    __shared__ float As[128][36];   // [m][k]
    __shared__ float Bs[128][36];   // [n][k]

    const int tid = threadIdx.x;
    const int wid = tid >> 5, lane = tid & 31;
    const int g = lane >> 2, tig = lane & 3;
    const int wm = wid >> 2, wn = wid & 3;
    const int m0 = blockIdx.y * 128, n0 = blockIdx.x * 128;

    const int row = tid >> 1, half = tid & 1;
    const float* pA = A  + (size_t)(m0 + row) * E_ + half * 16;
    const float* pB = Bw + (size_t)(n0 + row) * E_ + half * 16;

    float acc[4][4][4];
#pragma unroll
    for (int i = 0; i < 4; i++)
#pragma unroll
        for (int j = 0; j < 4; j++)
#pragma unroll
            for (int r = 0; r < 4; r++) acc[i][j][r] = 0.f;

    float4 fa[4], fb[4];
#pragma unroll
    for (int u = 0; u < 4; u++) {
        fa[u] = *(const float4*)(pA + u * 4);
        fb[u] = *(const float4*)(pB + u * 4);
    }

    for (int c = 0; c < 32; c++) {
#pragma unroll
        for (int u = 0; u < 4; u++) {
            const int kc = half * 16 + u * 4;
            *(float4*)&As[row][kc] = make_float4(tf32r(fa[u].x), tf32r(fa[u].y),
                                                 tf32r(fa[u].z), tf32r(fa[u].w));
            *(float4*)&Bs[row][kc] = make_float4(tf32r(fb[u].x), tf32r(fb[u].y),
                                                 tf32r(fb[u].z), tf32r(fb[u].w));
        }
        __syncthreads();
        if (c + 1 < 32) {
#pragma unroll
            for (int u = 0; u < 4; u++) {
                fa[u] = *(const float4*)(pA + (c + 1) * 32 + u * 4);
                fb[u] = *(const float4*)(pB + (c + 1) * 32 + u * 4);
            }
        }
#pragma unroll
        for (int k8 = 0; k8 < 32; k8 += 8) {
            u32 a[4][4], b[4][2];
#pragma unroll
            for (int mi = 0; mi < 4; mi++) {
                const int r = wm * 64 + mi * 16 + g;
                const u32* r0 = (const u32*)&As[r][k8 + tig];
                const u32* r1 = (const u32*)&As[r + 8][k8 + tig];
                a[mi][0] = r0[0]; a[mi][1] = r1[0];
                a[mi][2] = r0[4]; a[mi][3] = r1[4];
            }
#pragma unroll
            for (int ni = 0; ni < 4; ni++) {
                const int nn = wn * 32 + ni * 8 + g;
                const u32* r0 = (const u32*)&Bs[nn][k8 + tig];
                b[ni][0] = r0[0]; b[ni][1] = r0[4];
            }
#pragma unroll
            for (int mi = 0; mi < 4; mi++)
#pragma unroll
                for (int ni = 0; ni < 4; ni++)
                    mma8(acc[mi][ni], a[mi], b[ni]);
        }
        __syncthreads();
    }

#pragma unroll
    for (int mi = 0; mi < 4; mi++) {
#pragma unroll
        for (int hh = 0; hh < 2; hh++) {
            const int mg = m0 + wm * 64 + mi * 16 + g + hh * 8;
#pragma unroll
            for (int ni = 0; ni < 4; ni++) {
                const int col = n0 + wn * 32 + ni * 8 + 2 * tig;
                const float v0 = acc[mi][ni][hh * 2 + 0];
                const float v1 = acc[mi][ni][hh * 2 + 1];
                if (MODE == 0) {
                    *(float2*)&C[(size_t)mg * E_ + col] = make_float2(v0, v1);
                } else {
                    const int b = mg >> 11, s = mg & 2047;
                    const int h = col >> 6, d = col & 63;
                    *(float2*)&C[((size_t)(b * H_ + h) * S_ + s) * D_ + d] =
                        make_float2(v0, v1);
                }
            }
        }
    }
}

// ============================================================================
// tf32 mma.sync flash attention.
// CTA: 64 q-rows x one (b,h); 128 threads = 4 warps x 16 q-rows.
// Q fragments register-resident. k-tile = 64 keys.
// Ks[key][d] pad-68 (S-phase B frags conflict-free);
// Vt[d][key] pad-68 (PV B frags = adjacent float2 pairs via the
// col-permutation trick: P's C-frag feeds PV's A-frag directly).
// ============================================================================
__global__ __launch_bounds__(128) void attn_mma(const float* __restrict__ Q,
                                                const float* __restrict__ K,
                                                const float* __restrict__ V,
                                                float* __restrict__ AO) {
    __shared__ float Ks[64][68];
    __shared__ float Vt[64][68];

    const int tid = threadIdx.x;
    const int w = tid >> 5, lane = tid & 31;
    const int g = lane >> 2, tig = lane & 3;
    const int bh = blockIdx.y;
    const int q0 = blockIdx.x * 64;

    const float* Qb = Q + (size_t)bh * S_ * D_;
    const float* Kb = K + (size_t)bh * S_ * D_;
    const float* Vb = V + (size_t)bh * S_ * D_;

    const int frow  = tid & 63;          // fill row (key / q)
    const int fhalf = (tid >> 6) * 32;   // fill col half

    // ---- stage Q (scaled, tf32) through Ks, extract fragments ----
#pragma unroll
    for (int u = 0; u < 8; u++) {
        float4 v = *(const float4*)&Qb[(size_t)(q0 + frow) * D_ + fhalf + u * 4];
        Ks[frow][fhalf + u * 4 + 0] = tf32r(v.x * 0.125f);
        Ks[frow][fhalf + u * 4 + 1] = tf32r(v.y * 0.125f);
        Ks[frow][fhalf + u * 4 + 2] = tf32r(v.z * 0.125f);
        Ks[frow][fhalf + u * 4 + 3] = tf32r(v.w * 0.125f);
    }
    __syncthreads();
    u32 qf[8][4];
    {
        const int r = w * 16 + g;
#pragma unroll
        for (int k8 = 0; k8 < 8; k8++) {
            qf[k8][0] = __float_as_uint(Ks[r][k8 * 8 + tig]);
            qf[k8][1] = __float_as_uint(Ks[r + 8][k8 * 8 + tig]);
            qf[k8][2] = __float_as_uint(Ks[r][k8 * 8 + tig + 4]);
            qf[k8][3] = __float_as_uint(Ks[r + 8][k8 * 8 + tig + 4]);
        }
    }

    float m[2] = {-1e30f, -1e30f}, l[2] = {0.f, 0.f};
    float o[8][4];
#pragma unroll
    for (int j = 0; j < 8; j++)
#pragma unroll
        for (int r = 0; r < 4; r++) o[j][r] = 0.f;

    for (int k0 = 0; k0 < S_; k0 += 64) {
        __syncthreads();   // previous iter's Ks/Vt reads done (and Q extraction)
        // Ks[key][d]: coalesced copy. Vt[d][key]: transpose fill,
        // store bank = 4d+key -> 32 distinct banks, conflict-free.
#pragma unroll
        for (int u = 0; u < 8; u++) {
            float4 kv = *(const float4*)&Kb[(size_t)(k0 + frow) * D_ + fhalf + u * 4];
            Ks[frow][fhalf + u * 4 + 0] = tf32r(kv.x);
            Ks[frow][fhalf + u * 4 + 1] = tf32r(kv.y);
            Ks[frow][fhalf + u * 4 + 2] = tf32r(kv.z);
            Ks[frow][fhalf + u * 4 + 3] = tf32r(kv.w);
            float4 vv = *(const float4*)&Vb[(size_t)(k0 + frow) * D_ + fhalf + u * 4];
            Vt[fhalf + u * 4 + 0][frow] = tf32r(vv.x);
            Vt[fhalf + u * 4 + 1][frow] = tf32r(vv.y);
            Vt[fhalf + u * 4 + 2][frow] = tf32r(vv.z);
            Vt[fhalf + u * 4 + 3][frow] = tf32r(vv.w);
        }
        __syncthreads();

        // ---- S = Q @ K^T (16 q x 64 keys per warp) ----
        float s[8][4];
#pragma unroll
        for (int j = 0; j < 8; j++)
#pragma unroll
            for (int r = 0; r < 4; r++) s[j][r] = 0.f;
#pragma unroll
        for (int k8 = 0; k8 < 8; k8++) {
#pragma unroll
            for (int j = 0; j < 8; j++) {   // 8 independent accum chains
                const u32 b0 = __float_as_uint(Ks[j * 8 + g][k8 * 8 + tig]);
                const u32 b1 = __float_as_uint(Ks[j * 8 + g][k8 * 8 + tig + 4]);
                mma8v(s[j], qf[k8][0], qf[k8][1], qf[k8][2], qf[k8][3], b0, b1);
            }
        }

        // ---- online softmax in registers (rows g and g+8) ----
#pragma unroll
        for (int h = 0; h < 2; h++) {
            float mx = -1e30f;
#pragma unroll
            for (int j = 0; j < 8; j++)
                mx = fmaxf(mx, fmaxf(s[j][2 * h], s[j][2 * h + 1]));
            mx = fmaxf(mx, __shfl_xor_sync(0xffffffffu, mx, 1));
            mx = fmaxf(mx, __shfl_xor_sync(0xffffffffu, mx, 2));
            const float mn = fmaxf(m[h], mx);
            const float al = __expf(m[h] - mn);
            m[h] = mn;
            float rs = 0.f;
#pragma unroll
            for (int j = 0; j < 8; j++) {
                s[j][2 * h]     = __expf(s[j][2 * h] - mn);
                s[j][2 * h + 1] = __expf(s[j][2 * h + 1] - mn);
                rs += s[j][2 * h] + s[j][2 * h + 1];
            }
            rs += __shfl_xor_sync(0xffffffffu, rs, 1);
            rs += __shfl_xor_sync(0xffffffffu, rs, 2);
            l[h] = l[h] * al + rs;
#pragma unroll
            for (int j = 0; j < 8; j++) { o[j][2 * h] *= al; o[j][2 * h + 1] *= al; }
        }

        // ---- O += P @ V.  P's C-frag is fed as A-frag {c0,c2,c1,c3};
        // the implied key permutation (tig->2tig, tig+4->2tig+1) is absorbed
        // by loading V pairs Vt[d][8k8+2tig], [..+1] (one 8B load). ----
#pragma unroll
        for (int k8 = 0; k8 < 8; k8++) {
            const u32 a0 = tf32b(s[k8][0]);
            const u32 a1 = tf32b(s[k8][2]);
            const u32 a2 = tf32b(s[k8][1]);
            const u32 a3 = tf32b(s[k8][3]);
#pragma unroll
            for (int j = 0; j < 8; j++) {
                const float2 bv = *(const float2*)&Vt[j * 8 + g][k8 * 8 + 2 * tig];
                mma8v(o[j], a0, a1, a2, a3,
                      __float_as_uint(bv.x), __float_as_uint(bv.y));
            }
        }
    }

    // ---- normalize, write [B,S,E] ----
    const int b = bh >> 4, hd = bh & 15;
#pragma unroll
    for (int h = 0; h < 2; h++) {
        const float inv = 1.0f / l[h];
        const int row = q0 + w * 16 + g + h * 8;
#pragma unroll
        for (int j = 0; j < 8; j++) {
            *(float2*)&AO[((size_t)(b * S_ + row)) * E_ + hd * D_ + j * 8 + 2 * tig] =
                make_float2(o[j][2 * h] * inv, o[j][2 * h + 1] * inv);
        }
    }
}

extern "C" void kernel_launch(void* const* d_in, const int* in_sizes, int n_in,
                              void* d_out, int out_size) {
    (void)in_sizes; (void)n_in; (void)out_size;
    const float* x  = (const float*)d_in[0];
    const float* wq = (const float*)d_in[1];
    const float* wk = (const float*)d_in[2];
    const float* wv = (const float*)d_in[3];
    const float* wo = (const float*)d_in[4];
    float* out = (float*)d_out;

    float *q, *k, *v, *ao;
    cudaGetSymbolAddress((void**)&q,  g_Q);
    cudaGetSymbolAddress((void**)&k,  g_K);
    cudaGetSymbolAddress((void**)&v,  g_V);
    cudaGetSymbolAddress((void**)&ao, g_AO);

    const dim3 gp(E_ / 128, (B_ * S_) / 128);   // (8, 32)
    gemm_mma<1><<<gp, 256>>>(x, wq, q);      // Q -> [B,H,S,D]
    gemm_mma<1><<<gp, 256>>>(x, wk, k);      // K -> [B,H,S,D]
    gemm_mma<1><<<gp, 256>>>(x, wv, v);      // V -> [B,H,S,D]
    attn_mma<<<dim3(S_ / 64, B_ * H_), 128>>>(q, k, v, ao);
    gemm_mma<0><<<gp, 256>>>(ao, wo, out);   // out = AO @ wo^T
}

// round 11
// speedup vs baseline: 2.0890x; 1.0182x over previous
#include <cuda_runtime.h>
#include <math.h>

#define B_ 2
#define S_ 2048
#define E_ 1024
#define H_ 16
#define D_ 64

typedef unsigned int u32;

// Scratch (device globals — no allocation allowed in kernel_launch)
__device__ float g_Q [B_ * S_ * E_];   // [B,H,S,D]  tf32-rounded, pre-scaled 1/8
__device__ float g_K [B_ * S_ * E_];   // [B,H,S,D]  tf32-rounded
__device__ float g_V [B_ * S_ * E_];   // [B,H,D,S]  tf32-rounded (transposed)
__device__ float g_AO[B_ * S_ * E_];   // [B,S,E]

__device__ __forceinline__ u32 tf32b(float x) {   // tf32 (rna) bit pattern
    u32 r; asm("cvt.rna.tf32.f32 %0, %1;" : "=r"(r) : "f"(x));
    return r;
}
__device__ __forceinline__ float tf32r(float x) {
    return __uint_as_float(tf32b(x));
}
// D += A(16x8, row) * B(8x8, col)  -- tf32 inputs, fp32 accum (sm_80+ baseline)
__device__ __forceinline__ void mma8(float* c, const u32* a, const u32* b) {
    asm volatile(
        "mma.sync.aligned.m16n8k8.row.col.f32.tf32.tf32.f32 "
        "{%0,%1,%2,%3}, {%4,%5,%6,%7}, {%8,%9}, {%0,%1,%2,%3};"
        : "+f"(c[0]), "+f"(c[1]), "+f"(c[2]), "+f"(c[3])
        : "r"(a[0]), "r"(a[1]), "r"(a[2]), "r"(a[3]), "r"(b[0]), "r"(b[1]));
}
__device__ __forceinline__ void mma8v(float* c, u32 a0, u32 a1, u32 a2, u32 a3,
                                      u32 b0, u32 b1) {
    asm volatile(
        "mma.sync.aligned.m16n8k8.row.col.f32.tf32.tf32.f32 "
        "{%0,%1,%2,%3}, {%4,%5,%6,%7}, {%8,%9}, {%0,%1,%2,%3};"
        : "+f"(c[0]), "+f"(c[1]), "+f"(c[2]), "+f"(c[3])
        : "r"(a0), "r"(a1), "r"(a2), "r"(a3), "r"(b0), "r"(b1));
}
__device__ __forceinline__ u32 smem_u32(const void* p) {
    u32 a;
    asm("{ .reg .u64 t; cvta.to.shared.u64 t, %1; cvt.u32.u64 %0, t; }"
        : "=r"(a) : "l"(p));
    return a;
}
#define CP16(d, s) \
    asm volatile("cp.async.ca.shared.global [%0], [%1], 16;" :: "r"(d), "l"(s))
#define CPCOMMIT() asm volatile("cp.async.commit_group;" ::: "memory")
#define CPWAIT1()  asm volatile("cp.async.wait_group 1;" ::: "memory")

// ============================================================================
// tf32 mma.sync GEMM: C[4096,1024] = A[M,K] @ Bw[N,K]^T
// CTA tile 128x128, BK=32, 8 warps (2m x 4n), warp tile 64x32.
// MODE 0: C[M,N] fp32.
// MODE 1: [B,H,S,D], tf32-rounded, scaled by `scale` (attention operand prep).
// MODE 2: [B,H,D,S], tf32-rounded (V transposed for attention).
// ============================================================================
template <int MODE>
__global__ __launch_bounds__(256) void gemm_mma(const float* __restrict__ A,
                                                const float* __restrict__ Bw,
                                                float* __restrict__ C,
                                                float scale) {
    __shared__ float As[128][36];   // [m][k]
    __shared__ float Bs[128][36];   // [n][k]

    const int tid = threadIdx.x;
    const int wid = tid >> 5, lane = tid & 31;
    const int g = lane >> 2, tig = lane & 3;
    const int wm = wid >> 2, wn = wid & 3;
    const int m0 = blockIdx.y * 128, n0 = blockIdx.x * 128;

    const int row = tid >> 1, half = tid & 1;
    const float* pA = A  + (size_t)(m0 + row) * E_ + half * 16;
    const float* pB = Bw + (size_t)(n0 + row) * E_ + half * 16;

    float acc[4][4][4];
#pragma unroll
    for (int i = 0; i < 4; i++)
#pragma unroll
        for (int j = 0; j < 4; j++)
#pragma unroll
            for (int r = 0; r < 4; r++) acc[i][j][r] = 0.f;

    float4 fa[4], fb[4];
#pragma unroll
    for (int u = 0; u < 4; u++) {
        fa[u] = *(const float4*)(pA + u * 4);
        fb[u] = *(const float4*)(pB + u * 4);
    }

    for (int c = 0; c < 32; c++) {
#pragma unroll
        for (int u = 0; u < 4; u++) {
            const int kc = half * 16 + u * 4;
            *(float4*)&As[row][kc] = make_float4(tf32r(fa[u].x), tf32r(fa[u].y),
                                                 tf32r(fa[u].z), tf32r(fa[u].w));
            *(float4*)&Bs[row][kc] = make_float4(tf32r(fb[u].x), tf32r(fb[u].y),
                                                 tf32r(fb[u].z), tf32r(fb[u].w));
        }
        __syncthreads();
        if (c + 1 < 32) {
#pragma unroll
            for (int u = 0; u < 4; u++) {
                fa[u] = *(const float4*)(pA + (c + 1) * 32 + u * 4);
                fb[u] = *(const float4*)(pB + (c + 1) * 32 + u * 4);
            }
        }
#pragma unroll
        for (int k8 = 0; k8 < 32; k8 += 8) {
            u32 a[4][4], b[4][2];
#pragma unroll
            for (int mi = 0; mi < 4; mi++) {
                const int r = wm * 64 + mi * 16 + g;
                const u32* r0 = (const u32*)&As[r][k8 + tig];
                const u32* r1 = (const u32*)&As[r + 8][k8 + tig];
                a[mi][0] = r0[0]; a[mi][1] = r1[0];
                a[mi][2] = r0[4]; a[mi][3] = r1[4];
            }
#pragma unroll
            for (int ni = 0; ni < 4; ni++) {
                const int nn = wn * 32 + ni * 8 + g;
                const u32* r0 = (const u32*)&Bs[nn][k8 + tig];
                b[ni][0] = r0[0]; b[ni][1] = r0[4];
            }
#pragma unroll
            for (int mi = 0; mi < 4; mi++)
#pragma unroll
                for (int ni = 0; ni < 4; ni++)
                    mma8(acc[mi][ni], a[mi], b[ni]);
        }
        __syncthreads();
    }

#pragma unroll
    for (int mi = 0; mi < 4; mi++) {
#pragma unroll
        for (int hh = 0; hh < 2; hh++) {
            const int mg = m0 + wm * 64 + mi * 16 + g + hh * 8;
#pragma unroll
            for (int ni = 0; ni < 4; ni++) {
                const int col = n0 + wn * 32 + ni * 8 + 2 * tig;
                const float v0 = acc[mi][ni][hh * 2 + 0];
                const float v1 = acc[mi][ni][hh * 2 + 1];
                if (MODE == 0) {
                    *(float2*)&C[(size_t)mg * E_ + col] = make_float2(v0, v1);
                } else {
                    const int b = mg >> 11, s = mg & 2047;
                    const int h = col >> 6, d = col & 63;
                    if (MODE == 1) {
                        *(float2*)&C[((size_t)(b * H_ + h) * S_ + s) * D_ + d] =
                            make_float2(tf32r(v0 * scale), tf32r(v1 * scale));
                    } else {  // MODE 2: [B,H,D,S]
                        C[((size_t)(b * H_ + h) * D_ + d)     * S_ + s] = tf32r(v0 * scale);
                        C[((size_t)(b * H_ + h) * D_ + d + 1) * S_ + s] = tf32r(v1 * scale);
                    }
                }
            }
        }
    }
}

// ============================================================================
// tf32 mma.sync flash attention with cp.async double buffering.
// CTA: 64 q-rows x one (b,h); 128 threads = 4 warps x 16 q-rows.
// Operands arrive pre-tf32-rounded (Q pre-scaled); V pre-transposed [D,S].
// smem (dynamic, 69632B): Ks[2][64][68], Vt[2][64][68].
// ============================================================================
#define TILE 4352                    // 64*68 floats per buffer
#define SMEM_ATTN (4 * TILE * 4)     // 69632 bytes

__global__ __launch_bounds__(128) void attn_mma(const float* __restrict__ Q,
                                                const float* __restrict__ K,
                                                const float* __restrict__ V,
                                                float* __restrict__ AO) {
    extern __shared__ __align__(16) float sm[];
    const int tid = threadIdx.x;
    const int w = tid >> 5, lane = tid & 31;
    const int g = lane >> 2, tig = lane & 3;
    const int bh = blockIdx.y;
    const int q0 = blockIdx.x * 64;

    const float* Qb = Q + (size_t)bh * S_ * D_;
    const float* Kb = K + (size_t)bh * S_ * D_;
    const float* Vb = V + (size_t)bh * D_ * S_;   // [D,S]

    // ---- Q fragments straight from gmem (already tf32 + scaled) ----
    u32 qf[8][4];
    {
        const int r = q0 + w * 16 + g;
#pragma unroll
        for (int k8 = 0; k8 < 8; k8++) {
            qf[k8][0] = __float_as_uint(Qb[(size_t)r * D_ + k8 * 8 + tig]);
            qf[k8][1] = __float_as_uint(Qb[(size_t)(r + 8) * D_ + k8 * 8 + tig]);
            qf[k8][2] = __float_as_uint(Qb[(size_t)r * D_ + k8 * 8 + tig + 4]);
            qf[k8][3] = __float_as_uint(Qb[(size_t)(r + 8) * D_ + k8 * 8 + tig + 4]);
        }
    }

    const u32 sbase = smem_u32(sm);
    const int fr = tid >> 1;            // fill row (key / d)
    const int fh = (tid & 1) * 32;      // fill col half (floats)

    // prefetch one 64-key tile (K rows + V^T rows) into buffer bbuf
#define PREFETCH(k0v, bbuf) do {                                               \
    const u32 kd = sbase + (u32)(((bbuf) * TILE + fr * 68 + fh) * 4);          \
    const float* ksrc = Kb + (size_t)((k0v) + fr) * D_ + fh;                   \
    const u32 vd = sbase + (u32)(((2 + (bbuf)) * TILE + fr * 68 + fh) * 4);    \
    const float* vsrc = Vb + (size_t)fr * S_ + (k0v) + fh;                     \
    _Pragma("unroll")                                                          \
    for (int c2 = 0; c2 < 8; c2++) {                                           \
        CP16(kd + c2 * 16, ksrc + c2 * 4);                                     \
        CP16(vd + c2 * 16, vsrc + c2 * 4);                                     \
    }                                                                          \
} while (0)

    PREFETCH(0, 0);
    CPCOMMIT();

    float m[2] = {-1e30f, -1e30f}, l[2] = {0.f, 0.f};
    float o[8][4];
#pragma unroll
    for (int j = 0; j < 8; j++)
#pragma unroll
        for (int r = 0; r < 4; r++) o[j][r] = 0.f;

    for (int it = 0; it < S_ / 64; it++) {
        const int bf = it & 1;
        if (it + 1 < S_ / 64) PREFETCH((it + 1) * 64, bf ^ 1);
        CPCOMMIT();
        CPWAIT1();          // current tile's group complete (newest may pend)
        __syncthreads();    // all threads' fills visible

        const float* Ks = sm + bf * TILE;
        const float* Vt = sm + (2 + bf) * TILE;

        // ---- S = Q @ K^T (16 q x 64 keys per warp) ----
        float s[8][4];
#pragma unroll
        for (int j = 0; j < 8; j++)
#pragma unroll
            for (int r = 0; r < 4; r++) s[j][r] = 0.f;
#pragma unroll
        for (int k8 = 0; k8 < 8; k8++) {
#pragma unroll
            for (int j = 0; j < 8; j++) {
                const u32 b0 = __float_as_uint(Ks[(j * 8 + g) * 68 + k8 * 8 + tig]);
                const u32 b1 = __float_as_uint(Ks[(j * 8 + g) * 68 + k8 * 8 + tig + 4]);
                mma8v(s[j], qf[k8][0], qf[k8][1], qf[k8][2], qf[k8][3], b0, b1);
            }
        }

        // ---- online softmax in registers (rows g and g+8) ----
#pragma unroll
        for (int h = 0; h < 2; h++) {
            float mx = -1e30f;
#pragma unroll
            for (int j = 0; j < 8; j++)
                mx = fmaxf(mx, fmaxf(s[j][2 * h], s[j][2 * h + 1]));
            mx = fmaxf(mx, __shfl_xor_sync(0xffffffffu, mx, 1));
            mx = fmaxf(mx, __shfl_xor_sync(0xffffffffu, mx, 2));
            const float mn = fmaxf(m[h], mx);
            const float al = __expf(m[h] - mn);
            m[h] = mn;
            float rs = 0.f;
#pragma unroll
            for (int j = 0; j < 8; j++) {
                s[j][2 * h]     = __expf(s[j][2 * h] - mn);
                s[j][2 * h + 1] = __expf(s[j][2 * h + 1] - mn);
                rs += s[j][2 * h] + s[j][2 * h + 1];
            }
            rs += __shfl_xor_sync(0xffffffffu, rs, 1);
            rs += __shfl_xor_sync(0xffffffffu, rs, 2);
            l[h] = l[h] * al + rs;
#pragma unroll
            for (int j = 0; j < 8; j++) { o[j][2 * h] *= al; o[j][2 * h + 1] *= al; }
        }

        // ---- O += P @ V : P C-frag feeds A-frag {c0,c2,c1,c3}; implied key
        // permutation absorbed by V pair loads Vt[d][8k8+2tig..+1] ----
#pragma unroll
        for (int k8 = 0; k8 < 8; k8++) {
            const u32 a0 = tf32b(s[k8][0]);
            const u32 a1 = tf32b(s[k8][2]);
            const u32 a2 = tf32b(s[k8][1]);
            const u32 a3 = tf32b(s[k8][3]);
#pragma unroll
            for (int j = 0; j < 8; j++) {
                const float2 bv = *(const float2*)&Vt[(j * 8 + g) * 68 + k8 * 8 + 2 * tig];
                mma8v(o[j], a0, a1, a2, a3,
                      __float_as_uint(bv.x), __float_as_uint(bv.y));
            }
        }
        __syncthreads();   // done reading buffer bf before it is refilled
    }

    // ---- normalize, write [B,S,E] ----
    const int b = bh >> 4, hd = bh & 15;
#pragma unroll
    for (int h = 0; h < 2; h++) {
        const float inv = 1.0f / l[h];
        const int row = q0 + w * 16 + g + h * 8;
#pragma unroll
        for (int j = 0; j < 8; j++) {
            *(float2*)&AO[((size_t)(b * S_ + row)) * E_ + hd * D_ + j * 8 + 2 * tig] =
                make_float2(o[j][2 * h] * inv, o[j][2 * h + 1] * inv);
        }
    }
}

extern "C" void kernel_launch(void* const* d_in, const int* in_sizes, int n_in,
                              void* d_out, int out_size) {
    (void)in_sizes; (void)n_in; (void)out_size;
    const float* x  = (const float*)d_in[0];
    const float* wq = (const float*)d_in[1];
    const float* wk = (const float*)d_in[2];
    const float* wv = (const float*)d_in[3];
    const float* wo = (const float*)d_in[4];
    float* out = (float*)d_out;

    float *q, *k, *v, *ao;
    cudaGetSymbolAddress((void**)&q,  g_Q);
    cudaGetSymbolAddress((void**)&k,  g_K);
    cudaGetSymbolAddress((void**)&v,  g_V);
    cudaGetSymbolAddress((void**)&ao, g_AO);

    static int smem_set = 0;
    if (!smem_set) {
        cudaFuncSetAttribute(attn_mma, cudaFuncAttributeMaxDynamicSharedMemorySize,
                             SMEM_ATTN);
        smem_set = 1;
    }

    const dim3 gp(E_ / 128, (B_ * S_) / 128);   // (8, 32)
    gemm_mma<1><<<gp, 256>>>(x, wq, q, 0.125f);  // Q -> [B,H,S,D], tf32, scaled
    gemm_mma<1><<<gp, 256>>>(x, wk, k, 1.0f);    // K -> [B,H,S,D], tf32
    gemm_mma<2><<<gp, 256>>>(x, wv, v, 1.0f);    // V -> [B,H,D,S], tf32
    attn_mma<<<dim3(S_ / 64, B_ * H_), 128, SMEM_ATTN>>>(q, k, v, ao);
    gemm_mma<0><<<gp, 256>>>(ao, wo, out, 1.0f); // out = AO @ wo^T
}

// round 13
// speedup vs baseline: 2.1448x; 1.0267x over previous
#include <cuda_runtime.h>
#include <math.h>

#define B_ 2
#define S_ 2048
#define E_ 1024
#define H_ 16
#define D_ 64

typedef unsigned int u32;

// Scratch (device globals — no allocation allowed in kernel_launch)
// g_Q/g_K: [B,H,S,D] with d-permutation pi (pairs (t,t+4) adjacent), tf32,
//          Q pre-scaled by 1/8.  g_V: [B,H,D,S] tf32.  Consumed only by attn.
__device__ float g_Q [B_ * S_ * E_];
__device__ float g_K [B_ * S_ * E_];
__device__ float g_V [B_ * S_ * E_];
__device__ float g_AO[B_ * S_ * E_];   // [B,S,E]

__device__ __forceinline__ u32 tf32b(float x) {   // tf32 (rna) bit pattern
    u32 r; asm("cvt.rna.tf32.f32 %0, %1;" : "=r"(r) : "f"(x));
    return r;
}
__device__ __forceinline__ float tf32r(float x) {
    return __uint_as_float(tf32b(x));
}
// D += A(16x8, row) * B(8x8, col)  -- tf32 inputs, fp32 accum (sm_80+ baseline)
__device__ __forceinline__ void mma8(float* c, const u32* a, const u32* b) {
    asm volatile(
        "mma.sync.aligned.m16n8k8.row.col.f32.tf32.tf32.f32 "
        "{%0,%1,%2,%3}, {%4,%5,%6,%7}, {%8,%9}, {%0,%1,%2,%3};"
        : "+f"(c[0]), "+f"(c[1]), "+f"(c[2]), "+f"(c[3])
        : "r"(a[0]), "r"(a[1]), "r"(a[2]), "r"(a[3]), "r"(b[0]), "r"(b[1]));
}
__device__ __forceinline__ void mma8v(float* c, u32 a0, u32 a1, u32 a2, u32 a3,
                                      u32 b0, u32 b1) {
    asm volatile(
        "mma.sync.aligned.m16n8k8.row.col.f32.tf32.tf32.f32 "
        "{%0,%1,%2,%3}, {%4,%5,%6,%7}, {%8,%9}, {%0,%1,%2,%3};"
        : "+f"(c[0]), "+f"(c[1]), "+f"(c[2]), "+f"(c[3])
        : "r"(a0), "r"(a1), "r"(a2), "r"(a3), "r"(b0), "r"(b1));
}
__device__ __forceinline__ u32 smem_u32(const void* p) {
    u32 a;
    asm("{ .reg .u64 t; cvta.to.shared.u64 t, %1; cvt.u32.u64 %0, t; }"
        : "=r"(a) : "l"(p));
    return a;
}
#define CP16(d, s) \
    asm volatile("cp.async.ca.shared.global [%0], [%1], 16;" :: "r"(d), "l"(s))
#define CPCOMMIT() asm volatile("cp.async.commit_group;" ::: "memory")
#define CPWAIT1()  asm volatile("cp.async.wait_group 1;" ::: "memory")

// d-permutation within each 8-group: t<4 -> 2t ; t>=4 -> 2(t-4)+1
__device__ __forceinline__ int dperm(int c) {
    const int t = c & 7;
    return (c & ~7) + ((t < 4) ? 2 * t : 2 * (t - 4) + 1);
}

// ============================================================================
// tf32 mma.sync GEMM: C[4096,1024] = A[M,K] @ Bw[N,K]^T
// CTA tile 128x128, BK=32, 8 warps (2m x 4n), warp tile 64x32.
// MODE 0: C[M,N] fp32.
// MODE 1: [B,H,S,D], tf32, scaled, d-PERMUTED (attention Q/K prep).
// MODE 2: [B,H,D,S], tf32 (V transposed for attention).
// ============================================================================
template <int MODE>
__global__ __launch_bounds__(256) void gemm_mma(const float* __restrict__ A,
                                                const float* __restrict__ Bw,
                                                float* __restrict__ C,
                                                float scale) {
    __shared__ float As[128][36];   // [m][k]
    __shared__ float Bs[128][36];   // [n][k]

    const int tid = threadIdx.x;
    const int wid = tid >> 5, lane = tid & 31;
    const int g = lane >> 2, tig = lane & 3;
    const int wm = wid >> 2, wn = wid & 3;
    const int m0 = blockIdx.y * 128, n0 = blockIdx.x * 128;

    const int row = tid >> 1, half = tid & 1;
    const float* pA = A  + (size_t)(m0 + row) * E_ + half * 16;
    const float* pB = Bw + (size_t)(n0 + row) * E_ + half * 16;

    float acc[4][4][4];
#pragma unroll
    for (int i = 0; i < 4; i++)
#pragma unroll
        for (int j = 0; j < 4; j++)
#pragma unroll
            for (int r = 0; r < 4; r++) acc[i][j][r] = 0.f;

    float4 fa[4], fb[4];
#pragma unroll
    for (int u = 0; u < 4; u++) {
        fa[u] = *(const float4*)(pA + u * 4);
        fb[u] = *(const float4*)(pB + u * 4);
    }

    for (int c = 0; c < 32; c++) {
#pragma unroll
        for (int u = 0; u < 4; u++) {
            const int kc = half * 16 + u * 4;
            *(float4*)&As[row][kc] = make_float4(tf32r(fa[u].x), tf32r(fa[u].y),
                                                 tf32r(fa[u].z), tf32r(fa[u].w));
            *(float4*)&Bs[row][kc] = make_float4(tf32r(fb[u].x), tf32r(fb[u].y),
                                                 tf32r(fb[u].z), tf32r(fb[u].w));
        }
        __syncthreads();
        if (c + 1 < 32) {
#pragma unroll
            for (int u = 0; u < 4; u++) {
                fa[u] = *(const float4*)(pA + (c + 1) * 32 + u * 4);
                fb[u] = *(const float4*)(pB + (c + 1) * 32 + u * 4);
            }
        }
#pragma unroll
        for (int k8 = 0; k8 < 32; k8 += 8) {
            u32 a[4][4], b[4][2];
#pragma unroll
            for (int mi = 0; mi < 4; mi++) {
                const int r = wm * 64 + mi * 16 + g;
                const u32* r0 = (const u32*)&As[r][k8 + tig];
                const u32* r1 = (const u32*)&As[r + 8][k8 + tig];
                a[mi][0] = r0[0]; a[mi][1] = r1[0];
                a[mi][2] = r0[4]; a[mi][3] = r1[4];
            }
#pragma unroll
            for (int ni = 0; ni < 4; ni++) {
                const int nn = wn * 32 + ni * 8 + g;
                const u32* r0 = (const u32*)&Bs[nn][k8 + tig];
                b[ni][0] = r0[0]; b[ni][1] = r0[4];
            }
#pragma unroll
            for (int mi = 0; mi < 4; mi++)
#pragma unroll
                for (int ni = 0; ni < 4; ni++)
                    mma8(acc[mi][ni], a[mi], b[ni]);
        }
        __syncthreads();
    }

#pragma unroll
    for (int mi = 0; mi < 4; mi++) {
#pragma unroll
        for (int hh = 0; hh < 2; hh++) {
            const int mg = m0 + wm * 64 + mi * 16 + g + hh * 8;
#pragma unroll
            for (int ni = 0; ni < 4; ni++) {
                const int col = n0 + wn * 32 + ni * 8 + 2 * tig;
                const float v0 = acc[mi][ni][hh * 2 + 0];
                const float v1 = acc[mi][ni][hh * 2 + 1];
                if (MODE == 0) {
                    *(float2*)&C[(size_t)mg * E_ + col] = make_float2(v0, v1);
                } else {
                    const int b = mg >> 11, s = mg & 2047;
                    const int h = col >> 6, d = col & 63;
                    if (MODE == 1) {   // d-permuted scalar stores
                        float* base = &C[((size_t)(b * H_ + h) * S_ + s) * D_];
                        base[dperm(d)]     = tf32r(v0 * scale);
                        base[dperm(d + 1)] = tf32r(v1 * scale);
                    } else {  // MODE 2: [B,H,D,S]
                        C[((size_t)(b * H_ + h) * D_ + d)     * S_ + s] = tf32r(v0 * scale);
                        C[((size_t)(b * H_ + h) * D_ + d + 1) * S_ + s] = tf32r(v1 * scale);
                    }
                }
            }
        }
    }
}

// ============================================================================
// tf32 mma.sync flash attention, cp.async double-buffered, register-pipelined.
// CTA: 64 q-rows x one (b,h); 128 threads = 4 warps x 16 q-rows.
// Q/K arrive d-permuted (frag pairs adjacent -> LDS.64/LDG.64); V as [D,S].
// Ks/Vt stride 72 (== 8 mod 32): 64-bit frag loads conflict-free per phase.
// ============================================================================
#define KST 72
#define TILEF (64 * KST)             // floats per array per stage
#define SMEM_ATTN (4 * TILEF * 4)    // K0,K1,V0,V1 = 73728 B

__global__ void __launch_bounds__(128, 3)
attn_mma(const float* __restrict__ Q, const float* __restrict__ K,
         const float* __restrict__ V, float* __restrict__ AO) {
    extern __shared__ __align__(16) float sm[];
    const int tid = threadIdx.x;
    const int w = tid >> 5, lane = tid & 31;
    const int g = lane >> 2, tig = lane & 3;
    const int bh = blockIdx.y;
    const int q0 = blockIdx.x * 64;

    const float* Qb = Q + (size_t)bh * S_ * D_;
    const float* Kb = K + (size_t)bh * S_ * D_;
    const float* Vb = V + (size_t)bh * D_ * S_;   // [D,S]

    const u32 sbase = smem_u32(sm);
    const int fr = tid >> 1;            // fill row (key / d)
    const int fh = (tid & 1) * 32;      // fill col half (floats)

#define PREFETCH(k0v, bbuf) do {                                               \
    const u32 kd = sbase + (u32)(((bbuf) * TILEF + fr * KST + fh) * 4);        \
    const float* ksrc = Kb + (size_t)((k0v) + fr) * D_ + fh;                   \
    const u32 vd = sbase + (u32)(((2 + (bbuf)) * TILEF + fr * KST + fh) * 4);  \
    const float* vsrc = Vb + (size_t)fr * S_ + (k0v) + fh;                     \
    _Pragma("unroll")                                                          \
    for (int c2 = 0; c2 < 8; c2++) {                                           \
        CP16(kd + c2 * 16, ksrc + c2 * 4);                                     \
        CP16(vd + c2 * 16, vsrc + c2 * 4);                                     \
    }                                                                          \
} while (0)

    PREFETCH(0, 0);
    CPCOMMIT();

    // ---- Q fragments: permuted pairs -> one 8B load per (row, k8) ----
    u32 qf[8][4];
    {
        const int r = q0 + w * 16 + g;
#pragma unroll
        for (int k8 = 0; k8 < 8; k8++) {
            const float2 a = *(const float2*)&Qb[(size_t)r * D_ + k8 * 8 + 2 * tig];
            const float2 b = *(const float2*)&Qb[(size_t)(r + 8) * D_ + k8 * 8 + 2 * tig];
            qf[k8][0] = __float_as_uint(a.x); qf[k8][2] = __float_as_uint(a.y);
            qf[k8][1] = __float_as_uint(b.x); qf[k8][3] = __float_as_uint(b.y);
        }
    }

    float m[2] = {-1e30f, -1e30f}, l[2] = {0.f, 0.f};
    float o[8][4];
#pragma unroll
    for (int j = 0; j < 8; j++)
#pragma unroll
        for (int r = 0; r < 4; r++) o[j][r] = 0.f;

    const int frow = g * KST;   // row offset term reused (j*8+g)*KST = j*8*KST + frow

    for (int it = 0; it < S_ / 64; it++) {
        const int bf = it & 1;
        if (it + 1 < S_ / 64) PREFETCH((it + 1) * 64, bf ^ 1);
        CPCOMMIT();
        CPWAIT1();
        __syncthreads();

        const float* Ks = sm + bf * TILEF + frow + 2 * tig;
        const float* Vt = sm + (2 + bf) * TILEF + frow + 2 * tig;

        // ---- S = Q @ K^T, software-pipelined over k8 ----
        float s[8][4];
#pragma unroll
        for (int j = 0; j < 8; j++)
#pragma unroll
            for (int r = 0; r < 4; r++) s[j][r] = 0.f;

        float2 bK[8];
#pragma unroll
        for (int j = 0; j < 8; j++)
            bK[j] = *(const float2*)&Ks[j * 8 * KST];
#pragma unroll
        for (int k8 = 0; k8 < 8; k8++) {
            float2 bKn[8];
            if (k8 < 7) {
#pragma unroll
                for (int j = 0; j < 8; j++)
                    bKn[j] = *(const float2*)&Ks[j * 8 * KST + (k8 + 1) * 8];
            }
#pragma unroll
            for (int j = 0; j < 8; j++)
                mma8v(s[j], qf[k8][0], qf[k8][1], qf[k8][2], qf[k8][3],
                      __float_as_uint(bK[j].x), __float_as_uint(bK[j].y));
            if (k8 < 7) {
#pragma unroll
                for (int j = 0; j < 8; j++) bK[j] = bKn[j];
            }
        }

        // ---- online softmax in registers (rows g and g+8) ----
#pragma unroll
        for (int h = 0; h < 2; h++) {
            float mx = -1e30f;
#pragma unroll
            for (int j = 0; j < 8; j++)
                mx = fmaxf(mx, fmaxf(s[j][2 * h], s[j][2 * h + 1]));
            mx = fmaxf(mx, __shfl_xor_sync(0xffffffffu, mx, 1));
            mx = fmaxf(mx, __shfl_xor_sync(0xffffffffu, mx, 2));
            const float mn = fmaxf(m[h], mx);
            const float al = __expf(m[h] - mn);
            m[h] = mn;
            float rs = 0.f;
#pragma unroll
            for (int j = 0; j < 8; j++) {
                s[j][2 * h]     = __expf(s[j][2 * h] - mn);
                s[j][2 * h + 1] = __expf(s[j][2 * h + 1] - mn);
                rs += s[j][2 * h] + s[j][2 * h + 1];
            }
            rs += __shfl_xor_sync(0xffffffffu, rs, 1);
            rs += __shfl_xor_sync(0xffffffffu, rs, 2);
            l[h] = l[h] * al + rs;
#pragma unroll
            for (int j = 0; j < 8; j++) { o[j][2 * h] *= al; o[j][2 * h + 1] *= al; }
        }

        // ---- O += P @ V, software-pipelined; P C-frag feeds A-frag
        // {c0,c2,c1,c3}, key permutation absorbed by V pair loads ----
        float2 bV[8];
#pragma unroll
        for (int j = 0; j < 8; j++)
            bV[j] = *(const float2*)&Vt[j * 8 * KST];
#pragma unroll
        for (int k8 = 0; k8 < 8; k8++) {
            const u32 a0 = tf32b(s[k8][0]);
            const u32 a1 = tf32b(s[k8][2]);
            const u32 a2 = tf32b(s[k8][1]);
            const u32 a3 = tf32b(s[k8][3]);
            float2 bVn[8];
            if (k8 < 7) {
#pragma unroll
                for (int j = 0; j < 8; j++)
                    bVn[j] = *(const float2*)&Vt[j * 8 * KST + (k8 + 1) * 8];
            }
#pragma unroll
            for (int j = 0; j < 8; j++)
                mma8v(o[j], a0, a1, a2, a3,
                      __float_as_uint(bV[j].x), __float_as_uint(bV[j].y));
            if (k8 < 7) {
#pragma unroll
                for (int j = 0; j < 8; j++) bV[j] = bVn[j];
            }
        }
        __syncthreads();   // done reading buffer bf before refill
    }

    // ---- normalize, write [B,S,E] ----
    const int b = bh >> 4, hd = bh & 15;
#pragma unroll
    for (int h = 0; h < 2; h++) {
        const float inv = 1.0f / l[h];
        const int row = q0 + w * 16 + g + h * 8;
#pragma unroll
        for (int j = 0; j < 8; j++) {
            *(float2*)&AO[((size_t)(b * S_ + row)) * E_ + hd * D_ + j * 8 + 2 * tig] =
                make_float2(o[j][2 * h] * inv, o[j][2 * h + 1] * inv);
        }
    }
}

extern "C" void kernel_launch(void* const* d_in, const int* in_sizes, int n_in,
                              void* d_out, int out_size) {
    (void)in_sizes; (void)n_in; (void)out_size;
    const float* x  = (const float*)d_in[0];
    const float* wq = (const float*)d_in[1];
    const float* wk = (const float*)d_in[2];
    const float* wv = (const float*)d_in[3];
    const float* wo = (const float*)d_in[4];
    float* out = (float*)d_out;

    float *q, *k, *v, *ao;
    cudaGetSymbolAddress((void**)&q,  g_Q);
    cudaGetSymbolAddress((void**)&k,  g_K);
    cudaGetSymbolAddress((void**)&v,  g_V);
    cudaGetSymbolAddress((void**)&ao, g_AO);

    static int smem_set = 0;
    if (!smem_set) {
        cudaFuncSetAttribute(attn_mma, cudaFuncAttributeMaxDynamicSharedMemorySize,
                             SMEM_ATTN);
        smem_set = 1;
    }

    const dim3 gp(E_ / 128, (B_ * S_) / 128);   // (8, 32)
    gemm_mma<1><<<gp, 256>>>(x, wq, q, 0.125f);  // Q -> [B,H,S,D] perm, scaled
    gemm_mma<1><<<gp, 256>>>(x, wk, k, 1.0f);    // K -> [B,H,S,D] perm
    gemm_mma<2><<<gp, 256>>>(x, wv, v, 1.0f);    // V -> [B,H,D,S]
    attn_mma<<<dim3(S_ / 64, B_ * H_), 128, SMEM_ATTN>>>(q, k, v, ao);
    gemm_mma<0><<<gp, 256>>>(ao, wo, out, 1.0f); // out = AO @ wo^T
}